// round 1
// baseline (speedup 1.0000x reference)
#include <cuda_runtime.h>
#include <cstdint>

// Problem dims (fixed by dataset): X:(B,N), boundaries:(N,K+1), weight:(N,K,E), bias:(N,E)
#define BDIM 4096
#define NDIM 64
#define KDIM 128
#define EDIM 512
#define EPS_F 1e-8f

// Prefix table T[n][k][e], k in [0..K]:
//   T[n][k][e] = bias[n][e] + sum_{j<k} weight[n][j][e]
// out[b][n][e] = relu( T[n][bidx][e] + frac * (T[n][bidx+1][e] - T[n][bidx][e]) )
__device__ float g_T[(size_t)NDIM * (KDIM + 1) * EDIM];

// ---------------------------------------------------------------------------
// Kernel A: build prefix table. One thread per (n, e): serial scan over k.
// Coalesced across e (stride-1 within a warp). 32768 threads total.
// ---------------------------------------------------------------------------
__global__ void prefix_kernel(const float* __restrict__ weight,
                              const float* __restrict__ bias) {
    int t = blockIdx.x * blockDim.x + threadIdx.x;   // 0 .. N*E-1
    int n = t / EDIM;
    int e = t % EDIM;

    float acc = bias[n * EDIM + e];
    const float* wp = weight + (size_t)n * KDIM * EDIM + e;
    float*       Tp = g_T    + (size_t)n * (KDIM + 1) * EDIM + e;

#pragma unroll 8
    for (int k = 0; k < KDIM; k++) {
        Tp[(size_t)k * EDIM] = acc;
        acc += wp[(size_t)k * EDIM];
    }
    Tp[(size_t)KDIM * EDIM] = acc;
}

// ---------------------------------------------------------------------------
// Kernel B: gather + lerp + relu. One warp per (b, n) pair.
// Block = 256 threads = 8 warps = 8 consecutive b for a fixed n (blockIdx.y).
// Consecutive blocks share the same n -> that n's 264KB table slice stays hot
// in L2 while its wave executes.
// Each lane handles 4 float4 (16 floats) of the E=512 output row.
// ---------------------------------------------------------------------------
__global__ void gather_kernel(const float* __restrict__ X,
                              const float* __restrict__ bnd,
                              float* __restrict__ out) {
    const int lane = threadIdx.x & 31;
    const int warp = threadIdx.x >> 5;
    const int n = blockIdx.y;
    const int b = blockIdx.x * 8 + warp;

    const float x = X[(size_t)b * NDIM + n];
    const float* bn = bnd + (size_t)n * (KDIM + 1);

    // lower_bound over inner boundaries bn[1 .. K-1]  (K-1 elements)
    // bidx = count of inner elements strictly < x, in [0, K-1]
    int lo = 0, len = KDIM - 1;
    while (len > 0) {
        int half = len >> 1;
        bool pred = __ldg(&bn[1 + lo + half]) < x;
        lo  += pred ? (half + 1) : 0;
        len  = pred ? (len - half - 1) : half;
    }
    const float s  = __ldg(&bn[lo]);
    const float eb = __ldg(&bn[lo + 1]);
    const float frac = (x - s) / (eb - s + EPS_F);

    const float4* T0 = (const float4*)(g_T + ((size_t)n * (KDIM + 1) + lo) * EDIM);
    const float4* T1 = T0 + (EDIM / 4);
    float4* o = (float4*)(out + ((size_t)b * NDIM + n) * EDIM);

#pragma unroll
    for (int j = 0; j < 4; j++) {
        int i = lane + 32 * j;          // coalesced float4 across the warp
        float4 a = T0[i];
        float4 c = T1[i];
        float4 r;
        r.x = fmaxf(fmaf(frac, c.x - a.x, a.x), 0.0f);
        r.y = fmaxf(fmaf(frac, c.y - a.y, a.y), 0.0f);
        r.z = fmaxf(fmaf(frac, c.z - a.z, a.z), 0.0f);
        r.w = fmaxf(fmaf(frac, c.w - a.w, a.w), 0.0f);
        o[i] = r;
    }
}

extern "C" void kernel_launch(void* const* d_in, const int* in_sizes, int n_in,
                              void* d_out, int out_size) {
    const float* X      = (const float*)d_in[0];   // (B, N)
    const float* bnd    = (const float*)d_in[1];   // (N, K+1)
    const float* weight = (const float*)d_in[2];   // (N, K, E)
    const float* bias   = (const float*)d_in[3];   // (N, E)
    float* out = (float*)d_out;                    // (B, N, E)

    // Kernel A: N*E threads
    {
        int total = NDIM * EDIM;
        prefix_kernel<<<total / 256, 256>>>(weight, bias);
    }
    // Kernel B: warp per (b,n); grid.y = n so same-n blocks are contiguous
    {
        dim3 grid(BDIM / 8, NDIM);
        gather_kernel<<<grid, 256>>>(X, bnd, out);
    }
}

// round 2
// speedup vs baseline: 1.0405x; 1.0405x over previous
#include <cuda_runtime.h>
#include <cuda_fp16.h>
#include <cstdint>

// Problem dims (fixed): X:(B,N), boundaries:(N,K+1), weight:(N,K,E), bias:(N,E)
#define BDIM 4096
#define NDIM 64
#define KDIM 128
#define EDIM 512
#define EPS_F 1e-8f

// Prefix table T[n][k][e] (fp16), k in [0..K]:
//   T[n][k][e] = bias[n][e] + sum_{j<k} weight[n][j][e]   (fp32 accumulate, fp16 store)
// out[b][n][e] = relu( lerp(T[n][bidx][e], T[n][bidx+1][e], frac) )
__device__ __half g_T16[(size_t)NDIM * (KDIM + 1) * EDIM];

// ---------------------------------------------------------------------------
// Kernel A: build prefix table. 4 k-chunks of 32 per (n,e) for 4x parallelism
// (131072 threads). Chunk c redundantly sums k < 32c for its base, then scans
// its 32 entries. fp32 accumulation throughout; single fp16 round at store.
// ---------------------------------------------------------------------------
__global__ void prefix_kernel(const float* __restrict__ weight,
                              const float* __restrict__ bias) {
    int t = blockIdx.x * blockDim.x + threadIdx.x;   // 0 .. N*4*E-1
    int e   = t % EDIM;
    int tmp = t / EDIM;          // n*4 + c
    int c   = tmp & 3;
    int n   = tmp >> 2;

    const float* wp = weight + (size_t)n * KDIM * EDIM + e;
    __half*      Tp = g_T16  + (size_t)n * (KDIM + 1) * EDIM + e;

    float acc = bias[n * EDIM + e];
    const int k0 = c * 32;

#pragma unroll 8
    for (int k = 0; k < k0; k++)               // base: sum_{j<k0} w_j
        acc += wp[(size_t)k * EDIM];

#pragma unroll
    for (int k = k0; k < k0 + 32; k++) {       // scan this chunk
        Tp[(size_t)k * EDIM] = __float2half_rn(acc);
        acc += wp[(size_t)k * EDIM];
    }
    if (c == 3)
        Tp[(size_t)KDIM * EDIM] = __float2half_rn(acc);
}

// ---------------------------------------------------------------------------
// Kernel B: gather + lerp + relu. One warp per (b, n). Table rows are fp16
// (1 KB/row); each lane loads 2x uint4 (16 halves) per row, lerps in fp32,
// writes 4x float4. Same-n blocks adjacent so the 132KB/n fp16 slice stays
// hot in L1/L2.
// ---------------------------------------------------------------------------
__global__ void gather_kernel(const float* __restrict__ X,
                              const float* __restrict__ bnd,
                              float* __restrict__ out) {
    const int lane = threadIdx.x & 31;
    const int warp = threadIdx.x >> 5;
    const int n = blockIdx.y;
    const int b = blockIdx.x * 8 + warp;

    const float x = X[(size_t)b * NDIM + n];
    const float* bn = bnd + (size_t)n * (KDIM + 1);

    // lower_bound over inner boundaries bn[1 .. K-1]: bidx in [0, K-1]
    int lo = 0, len = KDIM - 1;
    while (len > 0) {
        int half = len >> 1;
        bool pred = __ldg(&bn[1 + lo + half]) < x;
        lo  += pred ? (half + 1) : 0;
        len  = pred ? (len - half - 1) : half;
    }
    const float s  = __ldg(&bn[lo]);
    const float eb = __ldg(&bn[lo + 1]);
    const float frac = (x - s) / (eb - s + EPS_F);

    const uint4* T0 = (const uint4*)(g_T16 + ((size_t)n * (KDIM + 1) + lo) * EDIM);
    const uint4* T1 = T0 + (EDIM / 8);             // next row (+512 halves)
    float4* o = (float4*)(out + ((size_t)b * NDIM + n) * EDIM);

#pragma unroll
    for (int j = 0; j < 2; j++) {
        int i = lane + 32 * j;                     // uint4 index in [0,64)
        uint4 a = __ldg(&T0[i]);
        uint4 cc = __ldg(&T1[i]);

        const unsigned* ap = &a.x;
        const unsigned* cp = &cc.x;
        float4 r0, r1;
        float* rp = &r0.x;                         // r0.x..w, r1.x..w contiguous? not guaranteed — unroll manually
#pragma unroll
        for (int q = 0; q < 4; q++) {
            float2 av = __half22float2(*(const __half2*)&ap[q]);
            float2 cv = __half22float2(*(const __half2*)&cp[q]);
            float v0 = fmaxf(fmaf(frac, cv.x - av.x, av.x), 0.0f);
            float v1 = fmaxf(fmaf(frac, cv.y - av.y, av.y), 0.0f);
            if (q == 0) { r0.x = v0; r0.y = v1; }
            else if (q == 1) { r0.z = v0; r0.w = v1; }
            else if (q == 2) { r1.x = v0; r1.y = v1; }
            else { r1.z = v0; r1.w = v1; }
        }
        (void)rp;
        o[2 * i]     = r0;
        o[2 * i + 1] = r1;
    }
}

extern "C" void kernel_launch(void* const* d_in, const int* in_sizes, int n_in,
                              void* d_out, int out_size) {
    const float* X      = (const float*)d_in[0];   // (B, N)
    const float* bnd    = (const float*)d_in[1];   // (N, K+1)
    const float* weight = (const float*)d_in[2];   // (N, K, E)
    const float* bias   = (const float*)d_in[3];   // (N, E)
    float* out = (float*)d_out;                    // (B, N, E)

    // Kernel A: N*4*E threads (4 k-chunks per (n,e))
    {
        int total = NDIM * 4 * EDIM;
        prefix_kernel<<<total / 256, 256>>>(weight, bias);
    }
    // Kernel B: warp per (b,n); grid.y = n keeps same-n blocks contiguous
    {
        dim3 grid(BDIM / 8, NDIM);
        gather_kernel<<<grid, 256>>>(X, bnd, out);
    }
}